// round 2
// baseline (speedup 1.0000x reference)
#include <cuda_runtime.h>
#include <cuda_bf16.h>

// RNN: out[n,t,:] = tanh(x[n,t,:]@Wx + b + h_{t-1}@Wh), h_{-1}=h0.
// N=64, T=512, D=256, H=256, all fp32.
//
// Kernel 1: xW = x@Wx + b -> g_xw (unchanged from R1).
// Kernel 2: recurrence, 64 clusters x 2 CTAs. CTA r owns columns
//   [r*128, r*128+128) with its Wh slice register-resident. Warps 0-3 use
//   k in [0,128), warps 4-7 k in [128,256). The group whose k-half equals
//   the locally-produced columns (ks==r) never waits on the mbarrier; only
//   the peer-half readers do, so fabric latency overlaps local compute.

#define ULL unsigned long long

static __device__ __forceinline__ ULL pk2(float lo, float hi) {
    ULL r; asm("mov.b64 %0, {%1,%2};" : "=l"(r) : "f"(lo), "f"(hi)); return r;
}
static __device__ __forceinline__ void upk2(ULL v, float& lo, float& hi) {
    asm("mov.b64 {%0,%1}, %2;" : "=f"(lo), "=f"(hi) : "l"(v));
}
static __device__ __forceinline__ ULL f2fma(ULL a, ULL b, ULL c) {
    ULL d; asm("fma.rn.f32x2 %0, %1, %2, %3;" : "=l"(d) : "l"(a), "l"(b), "l"(c)); return d;
}
static __device__ __forceinline__ ULL f2add(ULL a, ULL b) {
    ULL d; asm("add.rn.f32x2 %0, %1, %2;" : "=l"(d) : "l"(a), "l"(b)); return d;
}
static __device__ __forceinline__ unsigned int smem_u32(const void* p) {
    unsigned int a;
    asm("{ .reg .u64 t; cvta.to.shared.u64 t, %1; cvt.u32.u64 %0, t; }"
        : "=r"(a) : "l"(p));
    return a;
}
// tanh(x) = 1 - 2/(1 + e^{2x}); saturates correctly at +/-inf exponent.
static __device__ __forceinline__ float fast_tanh(float x) {
    float e = __expf(x + x);
    return 1.0f - __fdividef(2.0f, e + 1.0f);
}

// Scratch for the input projection (no cudaMalloc allowed).
__device__ float g_xw[64 * 512 * 256];

// ---------------------------------------------------------------------------
// Kernel 1: xW GEMM.  C[M=32768, H=256] = X[M,256] * Wx[256,256] + b
// ---------------------------------------------------------------------------
__global__ void __launch_bounds__(256) gemm_xw(const float* __restrict__ X,
                                               const float* __restrict__ Wx,
                                               const float* __restrict__ bias) {
    __shared__ __align__(16) float As[16][128];  // [k][m]
    __shared__ __align__(16) float Bs[16][128];  // [k][h]

    const int t    = threadIdx.x;
    const int m0   = blockIdx.x * 128;
    const int h0   = blockIdx.y * 128;
    const int warp = t >> 5;
    const int lane = t & 31;

    ULL acc[8][4];
#pragma unroll
    for (int p = 0; p < 8; p++)
#pragma unroll
        for (int c = 0; c < 4; c++) acc[p][c] = 0ULL;

    for (int k0 = 0; k0 < 256; k0 += 16) {
#pragma unroll
        for (int i = 0; i < 2; i++) {
            int s   = t * 2 + i;
            int row = s >> 2;
            int kq  = s & 3;
            float4 v = *(const float4*)&X[(size_t)(m0 + row) * 256 + k0 + kq * 4];
            As[kq * 4 + 0][row] = v.x;
            As[kq * 4 + 1][row] = v.y;
            As[kq * 4 + 2][row] = v.z;
            As[kq * 4 + 3][row] = v.w;
        }
#pragma unroll
        for (int i = 0; i < 2; i++) {
            int s  = t * 2 + i;
            int kr = s >> 5;
            int hq = s & 31;
            float4 v = *(const float4*)&Wx[(size_t)(k0 + kr) * 256 + h0 + hq * 4];
            *(float4*)&Bs[kr][hq * 4] = v;
        }
        __syncthreads();

#pragma unroll
        for (int kk = 0; kk < 16; kk++) {
            const ulonglong2* ar = (const ulonglong2*)&As[kk][warp * 16];
            ulonglong2 q0 = ar[0], q1 = ar[1], q2 = ar[2], q3 = ar[3];
            ULL ap[8] = {q0.x, q0.y, q1.x, q1.y, q2.x, q2.y, q3.x, q3.y};
            float4 bv = *(const float4*)&Bs[kk][lane * 4];
            ULL bs0 = pk2(bv.x, bv.x), bs1 = pk2(bv.y, bv.y);
            ULL bs2 = pk2(bv.z, bv.z), bs3 = pk2(bv.w, bv.w);
#pragma unroll
            for (int p = 0; p < 8; p++) {
                acc[p][0] = f2fma(ap[p], bs0, acc[p][0]);
                acc[p][1] = f2fma(ap[p], bs1, acc[p][1]);
                acc[p][2] = f2fma(ap[p], bs2, acc[p][2]);
                acc[p][3] = f2fma(ap[p], bs3, acc[p][3]);
            }
        }
        __syncthreads();
    }

    float4 bb = *(const float4*)&bias[h0 + lane * 4];
#pragma unroll
    for (int p = 0; p < 8; p++) {
        float lo0, hi0, lo1, hi1, lo2, hi2, lo3, hi3;
        upk2(acc[p][0], lo0, hi0);
        upk2(acc[p][1], lo1, hi1);
        upk2(acc[p][2], lo2, hi2);
        upk2(acc[p][3], lo3, hi3);
        int m = m0 + warp * 16 + p * 2;
        float4 r0 = make_float4(lo0 + bb.x, lo1 + bb.y, lo2 + bb.z, lo3 + bb.w);
        float4 r1 = make_float4(hi0 + bb.x, hi1 + bb.y, hi2 + bb.z, hi3 + bb.w);
        *(float4*)&g_xw[(size_t)m * 256 + h0 + lane * 4]       = r0;
        *(float4*)&g_xw[(size_t)(m + 1) * 256 + h0 + lane * 4] = r1;
    }
}

// ---------------------------------------------------------------------------
// Kernel 2: recurrence. grid = 128 blocks, cluster (2,1,1).
// ---------------------------------------------------------------------------
__global__ void __launch_bounds__(256, 1) __cluster_dims__(2, 1, 1)
rnn_scan(const float* __restrict__ h0g, const float* __restrict__ Wh,
         float* __restrict__ out) {
    __shared__ __align__(16) float h_buf[2][256];
    __shared__ float p_s[2][128];           // remote-group partials, by step parity
    __shared__ __align__(8) ULL mbar;

    const int t     = threadIdx.x;
    const int n     = blockIdx.x >> 1;
    const int r     = blockIdx.x & 1;
    const int jbase = r * 128;
    const int j     = t & 127;
    const int ks    = t >> 7;               // warps 0-3 -> 0, warps 4-7 -> 1
    const bool is_local = (ks == r);        // reads locally-produced h half

    // Register-resident weight slice: Wh[ks*128+k][jbase+j], k-pairs.
    ULL W2[64];
#pragma unroll
    for (int k2 = 0; k2 < 64; k2++) {
        float w0 = Wh[(size_t)(ks * 128 + 2 * k2) * 256 + jbase + j];
        float w1 = Wh[(size_t)(ks * 128 + 2 * k2 + 1) * 256 + jbase + j];
        W2[k2] = pk2(w0, w1);
    }

    h_buf[0][t] = h0g[(size_t)n * 256 + t];

    const unsigned int bar_local = smem_u32(&mbar);
    if (t == 0) {
        asm volatile("mbarrier.init.shared.b64 [%0], %1;"
                     :: "r"(bar_local), "r"(128) : "memory");
    }
    // Cluster-wide barrier: mbarrier init + h_buf[0] visible everywhere.
    asm volatile("barrier.cluster.arrive.aligned;" ::: "memory");
    asm volatile("barrier.cluster.wait.aligned;" ::: "memory");

    const unsigned int peer = r ^ 1;
    unsigned int rem_h[2] = {0, 0}, rem_bar;
    if (is_local) {
        unsigned int lh0 = smem_u32(&h_buf[0][jbase + j]);
        unsigned int lh1 = smem_u32(&h_buf[1][jbase + j]);
        asm("mapa.shared::cluster.u32 %0, %1, %2;" : "=r"(rem_h[0]) : "r"(lh0), "r"(peer));
        asm("mapa.shared::cluster.u32 %0, %1, %2;" : "=r"(rem_h[1]) : "r"(lh1), "r"(peer));
    }
    asm("mapa.shared::cluster.u32 %0, %1, %2;" : "=r"(rem_bar) : "r"(bar_local), "r"(peer));

    const float* xwp = g_xw + (size_t)n * 512 * 256 + jbase;
    float xw_cur = is_local ? xwp[j] : 0.f;

    for (int s = 0; s < 512; s++) {
        const int cur = s & 1;
        const int nxt = cur ^ 1;

        // Peer-half readers wait for the peer's end-of-(s-1) arrivals.
        if (!is_local && s > 0) {
            unsigned int par = (unsigned int)((s & 1) ^ 1);
            unsigned int done;
            asm volatile(
                "{ .reg .pred p; "
                "mbarrier.try_wait.parity.acquire.cluster.shared::cta.b64 p, [%1], %2; "
                "selp.b32 %0, 1, 0, p; }"
                : "=r"(done) : "r"(bar_local), "r"(par) : "memory");
            while (!done) {
                asm volatile(
                    "{ .reg .pred p; "
                    "mbarrier.try_wait.parity.acquire.cluster.shared::cta.b64 p, [%1], %2, 0x989680; "
                    "selp.b32 %0, 1, 0, p; }"
                    : "=r"(done) : "r"(bar_local), "r"(par) : "memory");
            }
        }

        // Partial dot over this group's 128 k's: 32x LDS.128, 4 FMA chains.
        const ulonglong2* hp = (const ulonglong2*)&h_buf[cur][ks * 128];
        ULL a0 = 0ULL, a1 = 0ULL, a2 = 0ULL, a3 = 0ULL;
#pragma unroll
        for (int q = 0; q < 32; q += 2) {
            ulonglong2 v0 = hp[q];
            ulonglong2 v1 = hp[q + 1];
            a0 = f2fma(v0.x, W2[2 * q],     a0);
            a1 = f2fma(v0.y, W2[2 * q + 1], a1);
            a2 = f2fma(v1.x, W2[2 * q + 2], a2);
            a3 = f2fma(v1.y, W2[2 * q + 3], a3);
        }
        ULL ss = f2add(f2add(a0, a1), f2add(a2, a3));
        float plo, phi;
        upk2(ss, plo, phi);
        float part = plo + phi;

        float xw_nxt = 0.f;
        if (is_local) {
            int sn = (s + 1 < 512) ? (s + 1) : s;
            xw_nxt = xwp[(size_t)sn * 256 + j];   // prefetch next step
        } else {
            p_s[cur][j] = part;                   // publish remote-half partial
        }
        __syncthreads();                          // p_s visible to combiners

        if (is_local) {
            float pre = xw_cur + part + p_s[cur][j];
            float hn  = fast_tanh(pre);
            // Push to peer first (fabric latency on the global critical path).
            asm volatile("st.shared::cluster.f32 [%0], %1;"
                         :: "r"(rem_h[nxt]), "f"(hn) : "memory");
            asm volatile("mbarrier.arrive.release.cluster.shared::cluster.b64 _, [%0];"
                         :: "r"(rem_bar) : "memory");
            h_buf[nxt][jbase + j] = hn;
            out[((size_t)n * 512 + s) * 256 + jbase + j] = hn;
            xw_cur = xw_nxt;
            // Local-half visibility within the local group only.
            asm volatile("bar.sync 1, 128;" ::: "memory");
        }
    }

    // Don't exit while the peer may still write into our SMEM.
    asm volatile("barrier.cluster.arrive.aligned;" ::: "memory");
    asm volatile("barrier.cluster.wait.aligned;" ::: "memory");
}

// ---------------------------------------------------------------------------
extern "C" void kernel_launch(void* const* d_in, const int* in_sizes, int n_in,
                              void* d_out, int out_size) {
    const float* x  = (const float*)d_in[0];  // (64,512,256)
    const float* h0 = (const float*)d_in[1];  // (64,256)
    const float* Wx = (const float*)d_in[2];  // (256,256)
    const float* Wh = (const float*)d_in[3];  // (256,256)
    const float* b  = (const float*)d_in[4];  // (256,)
    float* out = (float*)d_out;               // (64,512,256)

    dim3 g1(256, 2);
    gemm_xw<<<g1, 256>>>(x, Wx, b);
    rnn_scan<<<128, 256>>>(h0, Wh, out);
    (void)in_sizes; (void)n_in; (void)out_size;
}

// round 3
// speedup vs baseline: 1.3281x; 1.3281x over previous
#include <cuda_runtime.h>
#include <cuda_bf16.h>

// RNN: out[n,t,:] = tanh(x[n,t,:]@Wx + b + h_{t-1}@Wh), h_{-1}=h0.
// N=64, T=512, D=256, H=256, all fp32.
//
// Kernel 1: xW = x@Wx + b -> g_xw (SIMT f32x2 GEMM, unchanged).
// Kernel 2: recurrence, 64 clusters x 2 CTAs. CTA r owns output columns
//   [r*128, +128) with its Wh slice register-resident. Per step each CTA's
//   two k-groups compute partials in parallel; the combiner group (k-half ==
//   locally-produced columns) combines + tanh, writes its half locally, and
//   ONE elected thread bulk-copies the 512B half to the peer CTA with
//   mbarrier::complete_tx. One expect_tx(512) per step on the local barrier
//   replaces last round's 128 remote arrives.

#define ULL unsigned long long

static __device__ __forceinline__ ULL pk2(float lo, float hi) {
    ULL r; asm("mov.b64 %0, {%1,%2};" : "=l"(r) : "f"(lo), "f"(hi)); return r;
}
static __device__ __forceinline__ void upk2(ULL v, float& lo, float& hi) {
    asm("mov.b64 {%0,%1}, %2;" : "=f"(lo), "=f"(hi) : "l"(v));
}
static __device__ __forceinline__ ULL f2fma(ULL a, ULL b, ULL c) {
    ULL d; asm("fma.rn.f32x2 %0, %1, %2, %3;" : "=l"(d) : "l"(a), "l"(b), "l"(c)); return d;
}
static __device__ __forceinline__ ULL f2add(ULL a, ULL b) {
    ULL d; asm("add.rn.f32x2 %0, %1, %2;" : "=l"(d) : "l"(a), "l"(b)); return d;
}
static __device__ __forceinline__ unsigned int smem_u32(const void* p) {
    unsigned int a;
    asm("{ .reg .u64 t; cvta.to.shared.u64 t, %1; cvt.u32.u64 %0, t; }"
        : "=r"(a) : "l"(p));
    return a;
}
static __device__ __forceinline__ float fast_tanh(float x) {
    float e = __expf(x + x);
    return 1.0f - __fdividef(2.0f, e + 1.0f);
}
static __device__ __forceinline__ void wait_parity(unsigned int bar, unsigned int par) {
    unsigned int done;
    asm volatile(
        "{ .reg .pred p; "
        "mbarrier.try_wait.parity.acquire.cta.shared::cta.b64 p, [%1], %2; "
        "selp.b32 %0, 1, 0, p; }"
        : "=r"(done) : "r"(bar), "r"(par) : "memory");
    while (!done) {
        asm volatile(
            "{ .reg .pred p; "
            "mbarrier.try_wait.parity.acquire.cta.shared::cta.b64 p, [%1], %2, 0x989680; "
            "selp.b32 %0, 1, 0, p; }"
            : "=r"(done) : "r"(bar), "r"(par) : "memory");
    }
}

// Scratch for the input projection (no cudaMalloc allowed).
__device__ float g_xw[64 * 512 * 256];

// ---------------------------------------------------------------------------
// Kernel 1: xW GEMM.  C[M=32768, H=256] = X[M,256] * Wx[256,256] + b
// ---------------------------------------------------------------------------
__global__ void __launch_bounds__(256) gemm_xw(const float* __restrict__ X,
                                               const float* __restrict__ Wx,
                                               const float* __restrict__ bias) {
    __shared__ __align__(16) float As[16][128];  // [k][m]
    __shared__ __align__(16) float Bs[16][128];  // [k][h]

    const int t    = threadIdx.x;
    const int m0   = blockIdx.x * 128;
    const int h0   = blockIdx.y * 128;
    const int warp = t >> 5;
    const int lane = t & 31;

    ULL acc[8][4];
#pragma unroll
    for (int p = 0; p < 8; p++)
#pragma unroll
        for (int c = 0; c < 4; c++) acc[p][c] = 0ULL;

    for (int k0 = 0; k0 < 256; k0 += 16) {
#pragma unroll
        for (int i = 0; i < 2; i++) {
            int s   = t * 2 + i;
            int row = s >> 2;
            int kq  = s & 3;
            float4 v = *(const float4*)&X[(size_t)(m0 + row) * 256 + k0 + kq * 4];
            As[kq * 4 + 0][row] = v.x;
            As[kq * 4 + 1][row] = v.y;
            As[kq * 4 + 2][row] = v.z;
            As[kq * 4 + 3][row] = v.w;
        }
#pragma unroll
        for (int i = 0; i < 2; i++) {
            int s  = t * 2 + i;
            int kr = s >> 5;
            int hq = s & 31;
            float4 v = *(const float4*)&Wx[(size_t)(k0 + kr) * 256 + h0 + hq * 4];
            *(float4*)&Bs[kr][hq * 4] = v;
        }
        __syncthreads();

#pragma unroll
        for (int kk = 0; kk < 16; kk++) {
            const ulonglong2* ar = (const ulonglong2*)&As[kk][warp * 16];
            ulonglong2 q0 = ar[0], q1 = ar[1], q2 = ar[2], q3 = ar[3];
            ULL ap[8] = {q0.x, q0.y, q1.x, q1.y, q2.x, q2.y, q3.x, q3.y};
            float4 bv = *(const float4*)&Bs[kk][lane * 4];
            ULL bs0 = pk2(bv.x, bv.x), bs1 = pk2(bv.y, bv.y);
            ULL bs2 = pk2(bv.z, bv.z), bs3 = pk2(bv.w, bv.w);
#pragma unroll
            for (int p = 0; p < 8; p++) {
                acc[p][0] = f2fma(ap[p], bs0, acc[p][0]);
                acc[p][1] = f2fma(ap[p], bs1, acc[p][1]);
                acc[p][2] = f2fma(ap[p], bs2, acc[p][2]);
                acc[p][3] = f2fma(ap[p], bs3, acc[p][3]);
            }
        }
        __syncthreads();
    }

    float4 bb = *(const float4*)&bias[h0 + lane * 4];
#pragma unroll
    for (int p = 0; p < 8; p++) {
        float lo0, hi0, lo1, hi1, lo2, hi2, lo3, hi3;
        upk2(acc[p][0], lo0, hi0);
        upk2(acc[p][1], lo1, hi1);
        upk2(acc[p][2], lo2, hi2);
        upk2(acc[p][3], lo3, hi3);
        int m = m0 + warp * 16 + p * 2;
        float4 r0 = make_float4(lo0 + bb.x, lo1 + bb.y, lo2 + bb.z, lo3 + bb.w);
        float4 r1 = make_float4(hi0 + bb.x, hi1 + bb.y, hi2 + bb.z, hi3 + bb.w);
        *(float4*)&g_xw[(size_t)m * 256 + h0 + lane * 4]       = r0;
        *(float4*)&g_xw[(size_t)(m + 1) * 256 + h0 + lane * 4] = r1;
    }
}

// ---------------------------------------------------------------------------
// Kernel 2: recurrence. grid = 128 blocks, cluster (2,1,1).
// ---------------------------------------------------------------------------
__global__ void __launch_bounds__(256, 1) __cluster_dims__(2, 1, 1)
rnn_scan(const float* __restrict__ h0g, const float* __restrict__ Wh,
         float* __restrict__ out) {
    __shared__ __align__(16) float h_buf[2][256];
    __shared__ float p_s[2][128];      // non-combiner partials, by step parity
    __shared__ __align__(8) ULL mbar;

    const int t     = threadIdx.x;
    const int n     = blockIdx.x >> 1;
    const int r     = blockIdx.x & 1;
    const int jbase = r * 128;
    const int j     = t & 127;
    const int ks    = t >> 7;              // k-half this thread accumulates
    const bool comb = (ks == r);           // combiner group: k-half == local cols

    // Register-resident weight slice: Wh[ks*128+k][jbase+j], k-pairs.
    ULL W2[64];
#pragma unroll
    for (int k2 = 0; k2 < 64; k2++) {
        float w0 = Wh[(size_t)(ks * 128 + 2 * k2) * 256 + jbase + j];
        float w1 = Wh[(size_t)(ks * 128 + 2 * k2 + 1) * 256 + jbase + j];
        W2[k2] = pk2(w0, w1);
    }

    h_buf[0][t] = h0g[(size_t)n * 256 + t];

    const unsigned int bar_local = smem_u32(&mbar);
    if (t == 0) {
        asm volatile("mbarrier.init.shared.b64 [%0], %1;"
                     :: "r"(bar_local), "r"(1) : "memory");
    }
    // Cluster-wide barrier: mbarrier init + h_buf[0] visible everywhere.
    asm volatile("barrier.cluster.arrive.aligned;" ::: "memory");
    asm volatile("barrier.cluster.wait.aligned;" ::: "memory");

    const unsigned int peer = r ^ 1;
    // Remote targets: peer's h_buf[buf][jbase .. +128) and peer's barrier.
    unsigned int rem_dst[2], rem_bar;
    {
        unsigned int l0 = smem_u32(&h_buf[0][jbase]);
        unsigned int l1 = smem_u32(&h_buf[1][jbase]);
        asm("mapa.shared::cluster.u32 %0, %1, %2;" : "=r"(rem_dst[0]) : "r"(l0), "r"(peer));
        asm("mapa.shared::cluster.u32 %0, %1, %2;" : "=r"(rem_dst[1]) : "r"(l1), "r"(peer));
        asm("mapa.shared::cluster.u32 %0, %1, %2;" : "=r"(rem_bar) : "r"(bar_local), "r"(peer));
    }
    const unsigned int src_loc[2] = { smem_u32(&h_buf[0][jbase]),
                                      smem_u32(&h_buf[1][jbase]) };
    const bool lead = (t == (unsigned)jbase);   // elected combiner thread

    const float* xwp = g_xw + (size_t)n * 512 * 256 + jbase;
    float xw_cur = comb ? xwp[j] : 0.f;

    for (int s = 0; s < 512; s++) {
        const int cur = s & 1;
        const int nxt = cur ^ 1;

        // Prefetch next step's input projection (combiners only).
        float xw_nxt = 0.f;
        if (comb) {
            int sn = (s + 1 < 512) ? (s + 1) : s;
            xw_nxt = xwp[(size_t)sn * 256 + j];
        }

        // Partial dot over this group's 128 k's: 32x LDS.128, 4 FMA chains.
        const ulonglong2* hp = (const ulonglong2*)&h_buf[cur][ks * 128];
        ULL a0 = 0ULL, a1 = 0ULL, a2 = 0ULL, a3 = 0ULL;
#pragma unroll
        for (int q = 0; q < 32; q += 2) {
            ulonglong2 v0 = hp[q];
            ulonglong2 v1 = hp[q + 1];
            a0 = f2fma(v0.x, W2[2 * q],     a0);
            a1 = f2fma(v0.y, W2[2 * q + 1], a1);
            a2 = f2fma(v1.x, W2[2 * q + 2], a2);
            a3 = f2fma(v1.y, W2[2 * q + 3], a3);
        }
        ULL ss = f2add(f2add(a0, a1), f2add(a2, a3));
        float plo, phi;
        upk2(ss, plo, phi);
        float part = plo + phi;

        if (!comb) p_s[cur][j] = part;     // publish the other k-half
        __syncthreads();                   // p_s visible to combiners

        if (comb) {
            float pre = xw_cur + part + p_s[cur][j];
            float hn  = fast_tanh(pre);
            h_buf[nxt][jbase + j] = hn;                       // local half
            out[((size_t)n * 512 + s) * 256 + jbase + j] = hn;
            xw_cur = xw_nxt;
            // Combiner-group barrier: local half complete (writers==readers).
            asm volatile("bar.sync 1, 128;" ::: "memory");
            if (lead) {
                // Account for the peer's 512B landing in our h_buf[nxt].
                asm volatile("mbarrier.arrive.expect_tx.shared::cta.b64 _, [%0], %1;"
                             :: "r"(bar_local), "r"(512) : "memory");
                // Order generic smem writes before the async-proxy read.
                asm volatile("fence.proxy.async.shared::cta;" ::: "memory");
                // One bulk copy: our 512B half -> peer h_buf[nxt][jbase].
                asm volatile(
                    "cp.async.bulk.shared::cluster.shared::cta.mbarrier::complete_tx::bytes "
                    "[%0], [%1], %2, [%3];"
                    :: "r"(rem_dst[nxt]), "r"(src_loc[nxt]), "r"(512), "r"(rem_bar)
                    : "memory");
            }
        }

        // Everyone waits for the peer's half of h_buf[nxt] (acquire).
        wait_parity(bar_local, (unsigned)(s & 1));
    }

    // Don't exit while the peer may still write into our SMEM.
    asm volatile("barrier.cluster.arrive.aligned;" ::: "memory");
    asm volatile("barrier.cluster.wait.aligned;" ::: "memory");
}

// ---------------------------------------------------------------------------
extern "C" void kernel_launch(void* const* d_in, const int* in_sizes, int n_in,
                              void* d_out, int out_size) {
    const float* x  = (const float*)d_in[0];  // (64,512,256)
    const float* h0 = (const float*)d_in[1];  // (64,256)
    const float* Wx = (const float*)d_in[2];  // (256,256)
    const float* Wh = (const float*)d_in[3];  // (256,256)
    const float* b  = (const float*)d_in[4];  // (256,)
    float* out = (float*)d_out;               // (64,512,256)

    dim3 g1(256, 2);
    gemm_xw<<<g1, 256>>>(x, Wx, b);
    rnn_scan<<<128, 256>>>(h0, Wh, out);
    (void)in_sizes; (void)n_in; (void)out_size;
}